// round 16
// baseline (speedup 1.0000x reference)
#include <cuda_runtime.h>
#include <cuda_fp16.h>

#define NN 100000
#define NE 1600000
#define NPART 98   // ceil(NN/1024)

// ---------------- scratch (static device globals; no allocs) ----------------
__device__ int    g_cnt[NN];
__device__ int    g_off[NN + 1];
__device__ int    g_pos[NN];
__device__ int    g_part[NPART];
__device__ int    g_srcs[NE];
__device__ __half g_B0h[128 * 256];           // fp16, [n][k]; k<128: Wl0, k>=128: Wr0
__device__ __half g_B1h[128 * 128];           // fp16, [j][k]; j<64: Wl1 col j, j>=64: Wr1 col j-64
__device__ __half g_x16[(size_t)NN * 128];    // fp16 copy of x
__device__ __half g_m016[(size_t)NN * 128];   // mean-aggregated x (fp16)
__device__ __half g_r16[(size_t)NN * 128];    // root term x @ Wr0 + b0 (fp16)
__device__ __half g_h16[(size_t)NN * 128];    // relu'd layer-0 output (fp16)
__device__ __half g_y16[(size_t)NN * 64];     // y1 = h @ W_l1 (fp16 gather operand)
__device__ float  g_z1[(size_t)NN * 64];      // z1 = h @ W_r1 (fp32 root term)

// ---------------- mma / cp.async helpers ----------------
__device__ __forceinline__ unsigned sptr(const void* p) {
    return (unsigned)__cvta_generic_to_shared(p);
}
#define LDSM4(R, addr)                                                              \
    asm volatile("ldmatrix.sync.aligned.m8n8.x4.shared.b16 {%0,%1,%2,%3}, [%4];"    \
                 : "=r"((R)[0]), "=r"((R)[1]), "=r"((R)[2]), "=r"((R)[3])           \
                 : "r"(addr))
__device__ __forceinline__ void mma_f16(float* c, const unsigned* a, unsigned b0, unsigned b1) {
    asm volatile(
        "mma.sync.aligned.m16n8k16.row.col.f32.f16.f16.f32 "
        "{%0,%1,%2,%3},{%4,%5,%6,%7},{%8,%9},{%0,%1,%2,%3};"
        : "+f"(c[0]), "+f"(c[1]), "+f"(c[2]), "+f"(c[3])
        : "r"(a[0]), "r"(a[1]), "r"(a[2]), "r"(a[3]), "r"(b0), "r"(b1));
}
__device__ __forceinline__ void cpa16(unsigned dst, const void* src, bool pred) {
    int sz = pred ? 16 : 0;
    asm volatile("cp.async.cg.shared.global [%0], [%1], 16, %2;"
                 :: "r"(dst), "l"(src), "r"(sz));
}
#define CP_COMMIT() asm volatile("cp.async.commit_group;")
#define CP_WAIT1() asm volatile("cp.async.wait_group 1;")
#define CP_WAIT0() asm volatile("cp.async.wait_group 0;")

// ---------------- CSR build ----------------
// edge_index is int32 (JAX x64 disabled). Fused: edge count atomic + x -> fp16.
__global__ void k_count(const int* __restrict__ ei, const float* __restrict__ x) {
    int e = blockIdx.x * blockDim.x + threadIdx.x;
    if (e < NE) {
        unsigned d = (unsigned)ei[NE + e];
        if (d < NN) atomicAdd(&g_cnt[d], 1);
        size_t i = (size_t)e * 8;
        float4 v0 = *(const float4*)&x[i];
        float4 v1 = *(const float4*)&x[i + 4];
        __half2 h0 = __floats2half2_rn(v0.x, v0.y);
        __half2 h1 = __floats2half2_rn(v0.z, v0.w);
        __half2 h2 = __floats2half2_rn(v1.x, v1.y);
        __half2 h3 = __floats2half2_rn(v1.z, v1.w);
        uint4 packed;
        packed.x = *(unsigned*)&h0;
        packed.y = *(unsigned*)&h1;
        packed.z = *(unsigned*)&h2;
        packed.w = *(unsigned*)&h3;
        *(uint4*)&g_x16[i] = packed;
    }
}

__global__ void k_scanA() {
    int i = blockIdx.x * 1024 + threadIdx.x;
    int v = (i < NN) ? g_cnt[i] : 0;
    __shared__ int ws[32];
    int lane = threadIdx.x & 31, w = threadIdx.x >> 5;
#pragma unroll
    for (int d = 16; d; d >>= 1) v += __shfl_down_sync(~0u, v, d);
    if (!lane) ws[w] = v;
    __syncthreads();
    if (!w) {
        int s = ws[lane];
#pragma unroll
        for (int d = 16; d; d >>= 1) s += __shfl_down_sync(~0u, s, d);
        if (!lane) g_part[blockIdx.x] = s;
    }
}

__global__ void k_scanB() {
    int t = threadIdx.x;
    int lane = t & 31, w = t >> 5;
    int c = (t < NPART) ? g_part[t] : 0;
    int v = c;
#pragma unroll
    for (int d = 1; d < 32; d <<= 1) {
        int u = __shfl_up_sync(~0u, v, d);
        if (lane >= d) v += u;
    }
    __shared__ int ws[4];
    if (lane == 31) ws[w] = v;
    __syncthreads();
    int add = 0;
#pragma unroll
    for (int i = 0; i < 4; i++)
        if (i < w) add += ws[i];
    int incl = v + add;
    if (t < NPART) g_part[t] = incl - c;
    if (t == NPART - 1) g_off[NN] = incl;
}

__global__ void k_scanC() {
    int i = blockIdx.x * 1024 + threadIdx.x;
    int c = (i < NN) ? g_cnt[i] : 0;
    int v = c;
    int lane = threadIdx.x & 31, w = threadIdx.x >> 5;
#pragma unroll
    for (int d = 1; d < 32; d <<= 1) {
        int t = __shfl_up_sync(~0u, v, d);
        if (lane >= d) v += t;
    }
    __shared__ int ws[32];
    if (lane == 31) ws[w] = v;
    __syncthreads();
    if (!w) {
        int s = ws[lane];
#pragma unroll
        for (int d = 1; d < 32; d <<= 1) {
            int t = __shfl_up_sync(~0u, s, d);
            if (lane >= d) s += t;
        }
        ws[lane] = s;
    }
    __syncthreads();
    int excl = v - c + (w ? ws[w - 1] : 0) + g_part[blockIdx.x];
    if (i < NN) {
        g_off[i] = excl;
        g_pos[i] = excl;
    }
}

__global__ void k_scatter(const int* __restrict__ ei) {
    int e = blockIdx.x * blockDim.x + threadIdx.x;
    if (e < NE) {
        unsigned d = (unsigned)ei[NE + e];
        if (d < NN) {
            int p = atomicAdd(&g_pos[d], 1);
            unsigned s = (unsigned)ei[e];
            g_srcs[p] = (s < NN) ? (int)s : 0;
        }
    }
}

// ---------------- pack weights: transposed fp16 [n][k] ----------------
__global__ void k_pack(const float* __restrict__ Wl0, const float* __restrict__ Wr0,
                       const float* __restrict__ Wl1, const float* __restrict__ Wr1) {
    int i = blockIdx.x * blockDim.x + threadIdx.x;
    if (i < 128 * 256) {
        int n = i >> 8, k = i & 255;
        float v = (k < 128) ? Wl0[k * 128 + n] : Wr0[(k - 128) * 128 + n];
        g_B0h[i] = __float2half_rn(v);
    }
    if (i < 128 * 128) {
        int j = i >> 7, k = i & 127;
        float v = (j < 64) ? Wl1[k * 64 + j] : Wr1[k * 64 + (j - 64)];
        g_B1h[i] = __float2half_rn(v);
    }
}

// ---------------- input-space mean aggregation: m016 = mean(x16[src]) ----------------
__global__ void k_aggx() {
    int node = blockIdx.x * 8 + (threadIdx.x >> 5);
    int lane = threadIdx.x & 31;
    if (node >= NN) return;
    int beg = g_off[node], end = g_off[node + 1];
    float inv = 1.0f / (float)max(end - beg, 1);
    float4 a0 = make_float4(0.f, 0.f, 0.f, 0.f);
    float4 a1 = make_float4(0.f, 0.f, 0.f, 0.f);
    float4 a2 = make_float4(0.f, 0.f, 0.f, 0.f);
    float4 a3 = make_float4(0.f, 0.f, 0.f, 0.f);
    int e = beg;
    for (; e + 4 <= end; e += 4) {
        int s0 = g_srcs[e], s1 = g_srcs[e + 1], s2 = g_srcs[e + 2], s3 = g_srcs[e + 3];
        uint2 u0 = *(const uint2*)&g_x16[(size_t)s0 * 128 + lane * 4];
        uint2 u1 = *(const uint2*)&g_x16[(size_t)s1 * 128 + lane * 4];
        uint2 u2 = *(const uint2*)&g_x16[(size_t)s2 * 128 + lane * 4];
        uint2 u3 = *(const uint2*)&g_x16[(size_t)s3 * 128 + lane * 4];
        float2 p0 = __half22float2(*(__half2*)&u0.x), p1 = __half22float2(*(__half2*)&u0.y);
        float2 q0 = __half22float2(*(__half2*)&u1.x), q1 = __half22float2(*(__half2*)&u1.y);
        float2 r0 = __half22float2(*(__half2*)&u2.x), r1 = __half22float2(*(__half2*)&u2.y);
        float2 t0 = __half22float2(*(__half2*)&u3.x), t1 = __half22float2(*(__half2*)&u3.y);
        a0.x += p0.x; a0.y += p0.y; a0.z += p1.x; a0.w += p1.y;
        a1.x += q0.x; a1.y += q0.y; a1.z += q1.x; a1.w += q1.y;
        a2.x += r0.x; a2.y += r0.y; a2.z += r1.x; a2.w += r1.y;
        a3.x += t0.x; a3.y += t0.y; a3.z += t1.x; a3.w += t1.y;
    }
    for (; e < end; e++) {
        int s0 = g_srcs[e];
        uint2 u0 = *(const uint2*)&g_x16[(size_t)s0 * 128 + lane * 4];
        float2 p0 = __half22float2(*(__half2*)&u0.x), p1 = __half22float2(*(__half2*)&u0.y);
        a0.x += p0.x; a0.y += p0.y; a0.z += p1.x; a0.w += p1.y;
    }
    __half2 ha = __floats2half2_rn((a0.x + a1.x + a2.x + a3.x) * inv,
                                   (a0.y + a1.y + a2.y + a3.y) * inv);
    __half2 hb = __floats2half2_rn((a0.z + a1.z + a2.z + a3.z) * inv,
                                   (a0.w + a1.w + a2.w + a3.w) * inv);
    uint2 st;
    st.x = *(unsigned*)&ha;
    st.y = *(unsigned*)&hb;
    *(uint2*)&g_m016[(size_t)node * 128 + lane * 4] = st;
}

// ---------------- fp16 tensor-core GEMM (m16n8k16, fp32 accum), K=128 all phases ----
// PHASE 0 (R): A = x (fp32->fp16 cvt), B = B0h k:128..255 -> r16 = x@Wr0 + b0 (fp16)
// PHASE 1 (L): A = m016 (cp.async),    B = B0h k:0..127   -> h16 = relu(acc + r16)
// PHASE 2:     A = h16 (cp.async),     B = B1h            -> y16 (n<64) / z1 (n>=64)
#define SP 40  // smem row stride in halves (80B)
template <int PHASE>
__global__ __launch_bounds__(256, 2) void k_gemm(const float* __restrict__ x,
                                                 const float* __restrict__ bias) {
    const int BSTR = (PHASE == 2) ? 128 : 256;
    const int BOFF = (PHASE == 0) ? 128 : 0;
    const __half* __restrict__ Bh = (PHASE == 2) ? g_B1h : g_B0h;

    __shared__ __half As[2][128 * SP];
    __shared__ __half Bs[2][128 * SP];

    int tid = threadIdx.x;
    int lane = tid & 31;
    int wid = tid >> 5;
    int warp_m = (wid >> 1) * 32;
    int warp_n = (wid & 1) * 64;
    int m0b = blockIdx.x * 128;

    int aRow = tid >> 1;             // 0..127
    int hLo = (tid & 1) * 16;        // 0 or 16 (halves)
    int grow = m0b + aRow;

    float acc[2][8][4];
#pragma unroll
    for (int mi = 0; mi < 2; mi++)
#pragma unroll
        for (int ni = 0; ni < 8; ni++)
#pragma unroll
            for (int q = 0; q < 4; q++) acc[mi][ni][q] = 0.f;

    int mat = lane >> 3, r8 = lane & 7;

    auto compute = [&](int buf, int) {
#pragma unroll
        for (int ks = 0; ks < 32; ks += 16) {
            unsigned aF[2][4], bF[4][4];
#pragma unroll
            for (int mi = 0; mi < 2; mi++) {
                int row = warp_m + mi * 16 + (mat & 1) * 8 + r8;
                int col = ks + (mat >> 1) * 8;
                LDSM4(aF[mi], sptr(&As[buf][row * SP + col]));
            }
#pragma unroll
            for (int nt = 0; nt < 4; nt++) {
                int row = warp_n + nt * 16 + (mat >> 1) * 8 + r8;
                int col = ks + (mat & 1) * 8;
                LDSM4(bF[nt], sptr(&Bs[buf][row * SP + col]));
            }
#pragma unroll
            for (int mi = 0; mi < 2; mi++)
#pragma unroll
                for (int nt = 0; nt < 4; nt++) {
                    mma_f16(acc[mi][nt * 2 + 0], aF[mi], bF[nt][0], bF[nt][1]);
                    mma_f16(acc[mi][nt * 2 + 1], aF[mi], bF[nt][2], bF[nt][3]);
                }
        }
    };

    if (PHASE == 0) {
        // synchronous fills (A needs fp32->fp16 conversion)
        for (int k0 = 0; k0 < 128; k0 += 32) {
#pragma unroll
            for (int q = 0; q < 2; q++) {
                float4 u = make_float4(0.f, 0.f, 0.f, 0.f);
                float4 v = make_float4(0.f, 0.f, 0.f, 0.f);
                if (grow < NN) {
                    u = *(const float4*)&x[(size_t)grow * 128 + k0 + hLo + q * 8];
                    v = *(const float4*)&x[(size_t)grow * 128 + k0 + hLo + q * 8 + 4];
                }
                __half2 h0 = __floats2half2_rn(u.x, u.y);
                __half2 h1 = __floats2half2_rn(u.z, u.w);
                __half2 h2 = __floats2half2_rn(v.x, v.y);
                __half2 h3 = __floats2half2_rn(v.z, v.w);
                uint4 pk;
                pk.x = *(unsigned*)&h0;
                pk.y = *(unsigned*)&h1;
                pk.z = *(unsigned*)&h2;
                pk.w = *(unsigned*)&h3;
                *(uint4*)&As[0][aRow * SP + hLo + q * 8] = pk;
                uint4 bv = *(const uint4*)&Bh[(size_t)aRow * BSTR + BOFF + k0 + hLo + q * 8];
                *(uint4*)&Bs[0][aRow * SP + hLo + q * 8] = bv;
            }
            __syncthreads();
            compute(0, k0);
            __syncthreads();
        }
    } else {
        // cp.async double-buffered pipeline (A already fp16)
        const __half* __restrict__ A16 = (PHASE == 1) ? g_m016 : g_h16;
        auto fill = [&](int buf, int k0) {
#pragma unroll
            for (int q = 0; q < 2; q++) {
                cpa16(sptr(&As[buf][aRow * SP + hLo + q * 8]),
                      &A16[(size_t)grow * 128 + k0 + hLo + q * 8], grow < NN);
                cpa16(sptr(&Bs[buf][aRow * SP + hLo + q * 8]),
                      &Bh[(size_t)aRow * BSTR + BOFF + k0 + hLo + q * 8], true);
            }
            CP_COMMIT();
        };
        fill(0, 0);
        for (int t = 0; t < 4; t++) {
            if (t < 3) {
                fill((t + 1) & 1, (t + 1) * 32);
                CP_WAIT1();
            } else {
                CP_WAIT0();
            }
            __syncthreads();
            compute(t & 1, t * 32);
            __syncthreads();
        }
    }

    // ---- epilogue ----
    int rrow = lane >> 2;
    int cquad = (lane & 3) * 2;
#pragma unroll
    for (int mi = 0; mi < 2; mi++) {
        int r0 = m0b + warp_m + mi * 16 + rrow;
#pragma unroll
        for (int ni = 0; ni < 8; ni++) {
            int col = warp_n + ni * 8 + cquad;
            float* c = acc[mi][ni];
            if (PHASE == 0) {
                float b0v = bias[col], b1v = bias[col + 1];
                if (r0 < NN) {
                    __half2 hv = __floats2half2_rn(c[0] + b0v, c[1] + b1v);
                    *(unsigned*)&g_r16[(size_t)r0 * 128 + col] = *(unsigned*)&hv;
                }
                if (r0 + 8 < NN) {
                    __half2 hv = __floats2half2_rn(c[2] + b0v, c[3] + b1v);
                    *(unsigned*)&g_r16[(size_t)(r0 + 8) * 128 + col] = *(unsigned*)&hv;
                }
            } else if (PHASE == 1) {
                if (r0 < NN) {
                    float2 rr = __half22float2(*(const __half2*)&g_r16[(size_t)r0 * 128 + col]);
                    __half2 hv = __floats2half2_rn(fmaxf(c[0] + rr.x, 0.f), fmaxf(c[1] + rr.y, 0.f));
                    *(unsigned*)&g_h16[(size_t)r0 * 128 + col] = *(unsigned*)&hv;
                }
                if (r0 + 8 < NN) {
                    float2 rr = __half22float2(*(const __half2*)&g_r16[(size_t)(r0 + 8) * 128 + col]);
                    __half2 hv = __floats2half2_rn(fmaxf(c[2] + rr.x, 0.f), fmaxf(c[3] + rr.y, 0.f));
                    *(unsigned*)&g_h16[(size_t)(r0 + 8) * 128 + col] = *(unsigned*)&hv;
                }
            } else if (warp_n == 0) {  // y1 columns -> fp16 gather operand
                if (r0 < NN)
                    *(__half2*)&g_y16[(size_t)r0 * 64 + col] = __floats2half2_rn(c[0], c[1]);
                if (r0 + 8 < NN)
                    *(__half2*)&g_y16[(size_t)(r0 + 8) * 64 + col] = __floats2half2_rn(c[2], c[3]);
            } else {  // z1 columns (root term) -> fp32 exact
                int zc = col - 64;
                if (r0 < NN)
                    *(float2*)&g_z1[(size_t)r0 * 64 + zc] = make_float2(c[0], c[1]);
                if (r0 + 8 < NN)
                    *(float2*)&g_z1[(size_t)(r0 + 8) * 64 + zc] = make_float2(c[2], c[3]);
            }
        }
    }
}

// ---------------- layer-1 aggregate + bias + root ----------------
__global__ void k_agg2(const float* __restrict__ bias, float* __restrict__ out) {
    int node = blockIdx.x * 8 + (threadIdx.x >> 5);
    int lane = threadIdx.x & 31;
    if (node >= NN) return;
    int beg = g_off[node], end = g_off[node + 1];
    float inv = 1.0f / (float)max(end - beg, 1);
    float2 a0 = make_float2(0.f, 0.f), a1 = make_float2(0.f, 0.f);
    float2 a2 = make_float2(0.f, 0.f), a3 = make_float2(0.f, 0.f);
    int e = beg;
    for (; e + 4 <= end; e += 4) {
        int s0 = g_srcs[e], s1 = g_srcs[e + 1], s2 = g_srcs[e + 2], s3 = g_srcs[e + 3];
        float2 v0 = __half22float2(*(const __half2*)&g_y16[(size_t)s0 * 64 + lane * 2]);
        float2 v1 = __half22float2(*(const __half2*)&g_y16[(size_t)s1 * 64 + lane * 2]);
        float2 v2 = __half22float2(*(const __half2*)&g_y16[(size_t)s2 * 64 + lane * 2]);
        float2 v3 = __half22float2(*(const __half2*)&g_y16[(size_t)s3 * 64 + lane * 2]);
        a0.x += v0.x; a0.y += v0.y;
        a1.x += v1.x; a1.y += v1.y;
        a2.x += v2.x; a2.y += v2.y;
        a3.x += v3.x; a3.y += v3.y;
    }
    for (; e < end; e++) {
        int s0 = g_srcs[e];
        float2 v0 = __half22float2(*(const __half2*)&g_y16[(size_t)s0 * 64 + lane * 2]);
        a0.x += v0.x; a0.y += v0.y;
    }
    float2 z = *(const float2*)&g_z1[(size_t)node * 64 + lane * 2];
    float2 b = *(const float2*)&bias[lane * 2];
    float2 r;
    r.x = fmaf(a0.x + a1.x + a2.x + a3.x, inv, b.x + z.x);
    r.y = fmaf(a0.y + a1.y + a2.y + a3.y, inv, b.y + z.y);
    *(float2*)&out[(size_t)node * 64 + lane * 2] = r;
}

// ---------------- launch ----------------
extern "C" void kernel_launch(void* const* d_in, const int* in_sizes, int n_in,
                              void* d_out, int out_size) {
    const float* x = (const float*)d_in[0];
    const int* ei = (const int*)d_in[1];          // int32 edge_index [2, NE]
    const float* Wl0 = (const float*)d_in[2];
    const float* bl0 = (const float*)d_in[3];
    const float* Wr0 = (const float*)d_in[4];
    const float* Wl1 = (const float*)d_in[5];
    const float* bl1 = (const float*)d_in[6];
    const float* Wr1 = (const float*)d_in[7];
    float* out = (float*)d_out;

    static void* cnt_ptr = nullptr;
    static cudaStream_t s2 = nullptr;
    static cudaEvent_t evF = nullptr, evJ = nullptr;
    if (!cnt_ptr) {
        cudaGetSymbolAddress(&cnt_ptr, g_cnt);
        cudaStreamCreateWithFlags(&s2, cudaStreamNonBlocking);
        cudaEventCreateWithFlags(&evF, cudaEventDisableTiming);
        cudaEventCreateWithFlags(&evJ, cudaEventDisableTiming);
    }

    int mt = (NN + 127) / 128;  // 782

    // ---- fork: side stream computes pack + root GEMM (reads fp32 x; no CSR dep) ----
    cudaEventRecord(evF, 0);
    cudaStreamWaitEvent(s2, evF, 0);
    k_pack<<<(256 * 128 + 255) / 256, 256, 0, s2>>>(Wl0, Wr0, Wl1, Wr1);
    k_gemm<0><<<mt, 256, 0, s2>>>(x, bl0);     // r16 = x @ Wr0 + b0
    cudaEventRecord(evJ, s2);

    // ---- main stream: CSR build + input aggregation ----
    cudaMemsetAsync(cnt_ptr, 0, NN * sizeof(int));
    k_count<<<(NE + 255) / 256, 256>>>(ei, x); // + fused x->fp16
    k_scanA<<<NPART, 1024>>>();
    k_scanB<<<1, 128>>>();
    k_scanC<<<NPART, 1024>>>();
    k_scatter<<<(NE + 255) / 256, 256>>>(ei);
    k_aggx<<<(NN + 7) / 8, 256>>>();           // m016 = mean(x16[src])

    // ---- join, then dependent GEMM chain ----
    cudaStreamWaitEvent(0, evJ, 0);
    k_gemm<1><<<mt, 256>>>(nullptr, nullptr);  // h16 = relu(m016 @ Wl0 + r16)
    k_gemm<2><<<mt, 256>>>(nullptr, nullptr);  // y16 = h @ Wl1, z1 = h @ Wr1
    k_agg2<<<(NN + 7) / 8, 256>>>(bl1, out);   // out = mean_agg(y16) + b1 + z1
}

// round 17
// speedup vs baseline: 1.1158x; 1.1158x over previous
#include <cuda_runtime.h>
#include <cuda_fp16.h>

#define NN 100000
#define NE 1600000
#define NPART 98   // ceil(NN/1024)

// ---------------- scratch (static device globals; no allocs) ----------------
__device__ int    g_cnt[NN];
__device__ int    g_off[NN + 1];
__device__ int    g_pos[NN];
__device__ int    g_part[NPART];
__device__ int    g_srcs[NE];
__device__ __half g_B0h[128 * 256];           // fp16, [n][k]; k<128: Wl0, k>=128: Wr0
__device__ __half g_B1h[128 * 128];           // fp16, [j][k]; j<64: Wl1 col j, j>=64: Wr1 col j-64
__device__ __half g_x16[(size_t)NN * 128];    // fp16 copy of x
__device__ __half g_m016[(size_t)NN * 128];   // mean-aggregated x (fp16)
__device__ __half g_h16[(size_t)NN * 128];    // relu'd layer-0 output (fp16)
__device__ __half g_y16[(size_t)NN * 64];     // y1 = h @ W_l1 (fp16 gather operand)
__device__ float  g_z1[(size_t)NN * 64];      // z1 = h @ W_r1 (fp32 root term)

// ---------------- mma / cp.async helpers ----------------
__device__ __forceinline__ unsigned sptr(const void* p) {
    return (unsigned)__cvta_generic_to_shared(p);
}
#define LDSM4(R, addr)                                                              \
    asm volatile("ldmatrix.sync.aligned.m8n8.x4.shared.b16 {%0,%1,%2,%3}, [%4];"    \
                 : "=r"((R)[0]), "=r"((R)[1]), "=r"((R)[2]), "=r"((R)[3])           \
                 : "r"(addr))
__device__ __forceinline__ void mma_f16(float* c, const unsigned* a, unsigned b0, unsigned b1) {
    asm volatile(
        "mma.sync.aligned.m16n8k16.row.col.f32.f16.f16.f32 "
        "{%0,%1,%2,%3},{%4,%5,%6,%7},{%8,%9},{%0,%1,%2,%3};"
        : "+f"(c[0]), "+f"(c[1]), "+f"(c[2]), "+f"(c[3])
        : "r"(a[0]), "r"(a[1]), "r"(a[2]), "r"(a[3]), "r"(b0), "r"(b1));
}
__device__ __forceinline__ void cpa16(unsigned dst, const void* src, bool pred) {
    int sz = pred ? 16 : 0;
    asm volatile("cp.async.cg.shared.global [%0], [%1], 16, %2;"
                 :: "r"(dst), "l"(src), "r"(sz));
}
#define CP_COMMIT() asm volatile("cp.async.commit_group;")
#define CP_WAIT1() asm volatile("cp.async.wait_group 1;")
#define CP_WAIT0() asm volatile("cp.async.wait_group 0;")

// ---------------- CSR build ----------------
// edge_index is int32 (JAX x64 disabled). Fused: edge count atomic + x -> fp16.
__global__ void k_count(const int* __restrict__ ei, const float* __restrict__ x) {
    int e = blockIdx.x * blockDim.x + threadIdx.x;
    if (e < NE) {
        unsigned d = (unsigned)ei[NE + e];
        if (d < NN) atomicAdd(&g_cnt[d], 1);
        size_t i = (size_t)e * 8;
        float4 v0 = *(const float4*)&x[i];
        float4 v1 = *(const float4*)&x[i + 4];
        __half2 h0 = __floats2half2_rn(v0.x, v0.y);
        __half2 h1 = __floats2half2_rn(v0.z, v0.w);
        __half2 h2 = __floats2half2_rn(v1.x, v1.y);
        __half2 h3 = __floats2half2_rn(v1.z, v1.w);
        uint4 packed;
        packed.x = *(unsigned*)&h0;
        packed.y = *(unsigned*)&h1;
        packed.z = *(unsigned*)&h2;
        packed.w = *(unsigned*)&h3;
        *(uint4*)&g_x16[i] = packed;
    }
}

__global__ void k_scanA() {
    int i = blockIdx.x * 1024 + threadIdx.x;
    int v = (i < NN) ? g_cnt[i] : 0;
    __shared__ int ws[32];
    int lane = threadIdx.x & 31, w = threadIdx.x >> 5;
#pragma unroll
    for (int d = 16; d; d >>= 1) v += __shfl_down_sync(~0u, v, d);
    if (!lane) ws[w] = v;
    __syncthreads();
    if (!w) {
        int s = ws[lane];
#pragma unroll
        for (int d = 16; d; d >>= 1) s += __shfl_down_sync(~0u, s, d);
        if (!lane) g_part[blockIdx.x] = s;
    }
}

__global__ void k_scanB() {
    int t = threadIdx.x;
    int lane = t & 31, w = t >> 5;
    int c = (t < NPART) ? g_part[t] : 0;
    int v = c;
#pragma unroll
    for (int d = 1; d < 32; d <<= 1) {
        int u = __shfl_up_sync(~0u, v, d);
        if (lane >= d) v += u;
    }
    __shared__ int ws[4];
    if (lane == 31) ws[w] = v;
    __syncthreads();
    int add = 0;
#pragma unroll
    for (int i = 0; i < 4; i++)
        if (i < w) add += ws[i];
    int incl = v + add;
    if (t < NPART) g_part[t] = incl - c;
    if (t == NPART - 1) g_off[NN] = incl;
}

__global__ void k_scanC() {
    int i = blockIdx.x * 1024 + threadIdx.x;
    int c = (i < NN) ? g_cnt[i] : 0;
    int v = c;
    int lane = threadIdx.x & 31, w = threadIdx.x >> 5;
#pragma unroll
    for (int d = 1; d < 32; d <<= 1) {
        int t = __shfl_up_sync(~0u, v, d);
        if (lane >= d) v += t;
    }
    __shared__ int ws[32];
    if (lane == 31) ws[w] = v;
    __syncthreads();
    if (!w) {
        int s = ws[lane];
#pragma unroll
        for (int d = 1; d < 32; d <<= 1) {
            int t = __shfl_up_sync(~0u, s, d);
            if (lane >= d) s += t;
        }
        ws[lane] = s;
    }
    __syncthreads();
    int excl = v - c + (w ? ws[w - 1] : 0) + g_part[blockIdx.x];
    if (i < NN) {
        g_off[i] = excl;
        g_pos[i] = excl;
    }
}

__global__ void k_scatter(const int* __restrict__ ei) {
    int e = blockIdx.x * blockDim.x + threadIdx.x;
    if (e < NE) {
        unsigned d = (unsigned)ei[NE + e];
        if (d < NN) {
            int p = atomicAdd(&g_pos[d], 1);
            unsigned s = (unsigned)ei[e];
            g_srcs[p] = (s < NN) ? (int)s : 0;
        }
    }
}

// ---------------- pack weights: transposed fp16 [n][k] ----------------
__global__ void k_pack(const float* __restrict__ Wl0, const float* __restrict__ Wr0,
                       const float* __restrict__ Wl1, const float* __restrict__ Wr1) {
    int i = blockIdx.x * blockDim.x + threadIdx.x;
    if (i < 128 * 256) {
        int n = i >> 8, k = i & 255;
        float v = (k < 128) ? Wl0[k * 128 + n] : Wr0[(k - 128) * 128 + n];
        g_B0h[i] = __float2half_rn(v);
    }
    if (i < 128 * 128) {
        int j = i >> 7, k = i & 127;
        float v = (j < 64) ? Wl1[k * 64 + j] : Wr1[k * 64 + (j - 64)];
        g_B1h[i] = __float2half_rn(v);
    }
}

// ---------------- input-space mean aggregation: m016 = mean(x16[src]) ----------------
__global__ void k_aggx() {
    int node = blockIdx.x * 8 + (threadIdx.x >> 5);
    int lane = threadIdx.x & 31;
    if (node >= NN) return;
    int beg = g_off[node], end = g_off[node + 1];
    float inv = 1.0f / (float)max(end - beg, 1);
    float4 a0 = make_float4(0.f, 0.f, 0.f, 0.f);
    float4 a1 = make_float4(0.f, 0.f, 0.f, 0.f);
    float4 a2 = make_float4(0.f, 0.f, 0.f, 0.f);
    float4 a3 = make_float4(0.f, 0.f, 0.f, 0.f);
    int e = beg;
    for (; e + 4 <= end; e += 4) {
        int s0 = g_srcs[e], s1 = g_srcs[e + 1], s2 = g_srcs[e + 2], s3 = g_srcs[e + 3];
        uint2 u0 = *(const uint2*)&g_x16[(size_t)s0 * 128 + lane * 4];
        uint2 u1 = *(const uint2*)&g_x16[(size_t)s1 * 128 + lane * 4];
        uint2 u2 = *(const uint2*)&g_x16[(size_t)s2 * 128 + lane * 4];
        uint2 u3 = *(const uint2*)&g_x16[(size_t)s3 * 128 + lane * 4];
        float2 p0 = __half22float2(*(__half2*)&u0.x), p1 = __half22float2(*(__half2*)&u0.y);
        float2 q0 = __half22float2(*(__half2*)&u1.x), q1 = __half22float2(*(__half2*)&u1.y);
        float2 r0 = __half22float2(*(__half2*)&u2.x), r1 = __half22float2(*(__half2*)&u2.y);
        float2 t0 = __half22float2(*(__half2*)&u3.x), t1 = __half22float2(*(__half2*)&u3.y);
        a0.x += p0.x; a0.y += p0.y; a0.z += p1.x; a0.w += p1.y;
        a1.x += q0.x; a1.y += q0.y; a1.z += q1.x; a1.w += q1.y;
        a2.x += r0.x; a2.y += r0.y; a2.z += r1.x; a2.w += r1.y;
        a3.x += t0.x; a3.y += t0.y; a3.z += t1.x; a3.w += t1.y;
    }
    for (; e < end; e++) {
        int s0 = g_srcs[e];
        uint2 u0 = *(const uint2*)&g_x16[(size_t)s0 * 128 + lane * 4];
        float2 p0 = __half22float2(*(__half2*)&u0.x), p1 = __half22float2(*(__half2*)&u0.y);
        a0.x += p0.x; a0.y += p0.y; a0.z += p1.x; a0.w += p1.y;
    }
    __half2 ha = __floats2half2_rn((a0.x + a1.x + a2.x + a3.x) * inv,
                                   (a0.y + a1.y + a2.y + a3.y) * inv);
    __half2 hb = __floats2half2_rn((a0.z + a1.z + a2.z + a3.z) * inv,
                                   (a0.w + a1.w + a2.w + a3.w) * inv);
    uint2 st;
    st.x = *(unsigned*)&ha;
    st.y = *(unsigned*)&hb;
    *(uint2*)&g_m016[(size_t)node * 128 + lane * 4] = st;
}

// ---------------- fp16 tensor-core GEMM (m16n8k16, fp32 accum) ----------------
// BM=128, BN=128, BK=32 halves; 256 threads = 8 warps (4m x 2n); 2 CTA/SM.
// cp.async double-buffered fills (A operands all fp16).
// PHASE 0: C = concat(m016, x16) @ B0h (K=256), epilogue bias+relu -> h16 (fp16)
// PHASE 1: C = h16 @ B1h (K=128); warp_n==0 -> y16 (fp16), warp_n==64 -> z1 (fp32)
#define SP 40  // smem row stride in halves (80B)
template <int PHASE>
__global__ __launch_bounds__(256, 2) void k_gemm(const float* __restrict__ bias) {
    const int K = (PHASE == 0) ? 256 : 128;
    const int NT = K / 32;
    const __half* __restrict__ Bh = (PHASE == 0) ? g_B0h : g_B1h;

    __shared__ __half As[2][128 * SP];
    __shared__ __half Bs[2][128 * SP];

    int tid = threadIdx.x;
    int lane = tid & 31;
    int wid = tid >> 5;
    int warp_m = (wid >> 1) * 32;
    int warp_n = (wid & 1) * 64;
    int m0b = blockIdx.x * 128;

    int aRow = tid >> 1;             // 0..127
    int hLo = (tid & 1) * 16;        // 0 or 16 (halves)
    int grow = m0b + aRow;
    bool rowOk = grow < NN;

    float acc[2][8][4];
#pragma unroll
    for (int mi = 0; mi < 2; mi++)
#pragma unroll
        for (int ni = 0; ni < 8; ni++)
#pragma unroll
            for (int q = 0; q < 4; q++) acc[mi][ni][q] = 0.f;

    int mat = lane >> 3, r8 = lane & 7;

    auto fill = [&](int buf, int k0) {
        const __half* __restrict__ A16 =
            (PHASE == 0) ? ((k0 < 128) ? g_m016 : g_x16) : g_h16;
        int kk = (PHASE == 0) ? (k0 & 127) : k0;
#pragma unroll
        for (int q = 0; q < 2; q++) {
            cpa16(sptr(&As[buf][aRow * SP + hLo + q * 8]),
                  &A16[(size_t)grow * 128 + kk + hLo + q * 8], rowOk);
            cpa16(sptr(&Bs[buf][aRow * SP + hLo + q * 8]),
                  &Bh[(size_t)aRow * K + k0 + hLo + q * 8], true);
        }
        CP_COMMIT();
    };

    auto compute = [&](int buf) {
#pragma unroll
        for (int ks = 0; ks < 32; ks += 16) {
            unsigned aF[2][4], bF[4][4];
#pragma unroll
            for (int mi = 0; mi < 2; mi++) {
                int row = warp_m + mi * 16 + (mat & 1) * 8 + r8;
                int col = ks + (mat >> 1) * 8;
                LDSM4(aF[mi], sptr(&As[buf][row * SP + col]));
            }
#pragma unroll
            for (int nt = 0; nt < 4; nt++) {
                int row = warp_n + nt * 16 + (mat >> 1) * 8 + r8;
                int col = ks + (mat & 1) * 8;
                LDSM4(bF[nt], sptr(&Bs[buf][row * SP + col]));
            }
#pragma unroll
            for (int mi = 0; mi < 2; mi++)
#pragma unroll
                for (int nt = 0; nt < 4; nt++) {
                    mma_f16(acc[mi][nt * 2 + 0], aF[mi], bF[nt][0], bF[nt][1]);
                    mma_f16(acc[mi][nt * 2 + 1], aF[mi], bF[nt][2], bF[nt][3]);
                }
        }
    };

    fill(0, 0);
    for (int t = 0; t < NT; t++) {
        if (t + 1 < NT) {
            fill((t + 1) & 1, (t + 1) * 32);
            CP_WAIT1();
        } else {
            CP_WAIT0();
        }
        __syncthreads();
        compute(t & 1);
        __syncthreads();
    }

    // ---- epilogue ----
    int rrow = lane >> 2;
    int cquad = (lane & 3) * 2;
#pragma unroll
    for (int mi = 0; mi < 2; mi++) {
        int r0 = m0b + warp_m + mi * 16 + rrow;
#pragma unroll
        for (int ni = 0; ni < 8; ni++) {
            int col = warp_n + ni * 8 + cquad;
            float* c = acc[mi][ni];
            if (PHASE == 0) {
                float b0v = bias[col], b1v = bias[col + 1];
                if (r0 < NN) {
                    __half2 hv = __floats2half2_rn(fmaxf(c[0] + b0v, 0.f), fmaxf(c[1] + b1v, 0.f));
                    *(unsigned*)&g_h16[(size_t)r0 * 128 + col] = *(unsigned*)&hv;
                }
                if (r0 + 8 < NN) {
                    __half2 hv = __floats2half2_rn(fmaxf(c[2] + b0v, 0.f), fmaxf(c[3] + b1v, 0.f));
                    *(unsigned*)&g_h16[(size_t)(r0 + 8) * 128 + col] = *(unsigned*)&hv;
                }
            } else if (warp_n == 0) {  // y1 columns -> fp16 gather operand
                if (r0 < NN)
                    *(__half2*)&g_y16[(size_t)r0 * 64 + col] = __floats2half2_rn(c[0], c[1]);
                if (r0 + 8 < NN)
                    *(__half2*)&g_y16[(size_t)(r0 + 8) * 64 + col] = __floats2half2_rn(c[2], c[3]);
            } else {  // z1 columns (root term) -> fp32 exact
                int zc = col - 64;
                if (r0 < NN)
                    *(float2*)&g_z1[(size_t)r0 * 64 + zc] = make_float2(c[0], c[1]);
                if (r0 + 8 < NN)
                    *(float2*)&g_z1[(size_t)(r0 + 8) * 64 + zc] = make_float2(c[2], c[3]);
            }
        }
    }
}

// ---------------- layer-1 aggregate + bias + root ----------------
__global__ void k_agg2(const float* __restrict__ bias, float* __restrict__ out) {
    int node = blockIdx.x * 8 + (threadIdx.x >> 5);
    int lane = threadIdx.x & 31;
    if (node >= NN) return;
    int beg = g_off[node], end = g_off[node + 1];
    float inv = 1.0f / (float)max(end - beg, 1);
    float2 a0 = make_float2(0.f, 0.f), a1 = make_float2(0.f, 0.f);
    float2 a2 = make_float2(0.f, 0.f), a3 = make_float2(0.f, 0.f);
    int e = beg;
    for (; e + 4 <= end; e += 4) {
        int s0 = g_srcs[e], s1 = g_srcs[e + 1], s2 = g_srcs[e + 2], s3 = g_srcs[e + 3];
        float2 v0 = __half22float2(*(const __half2*)&g_y16[(size_t)s0 * 64 + lane * 2]);
        float2 v1 = __half22float2(*(const __half2*)&g_y16[(size_t)s1 * 64 + lane * 2]);
        float2 v2 = __half22float2(*(const __half2*)&g_y16[(size_t)s2 * 64 + lane * 2]);
        float2 v3 = __half22float2(*(const __half2*)&g_y16[(size_t)s3 * 64 + lane * 2]);
        a0.x += v0.x; a0.y += v0.y;
        a1.x += v1.x; a1.y += v1.y;
        a2.x += v2.x; a2.y += v2.y;
        a3.x += v3.x; a3.y += v3.y;
    }
    for (; e < end; e++) {
        int s0 = g_srcs[e];
        float2 v0 = __half22float2(*(const __half2*)&g_y16[(size_t)s0 * 64 + lane * 2]);
        a0.x += v0.x; a0.y += v0.y;
    }
    float2 z = *(const float2*)&g_z1[(size_t)node * 64 + lane * 2];
    float2 b = *(const float2*)&bias[lane * 2];
    float2 r;
    r.x = fmaf(a0.x + a1.x + a2.x + a3.x, inv, b.x + z.x);
    r.y = fmaf(a0.y + a1.y + a2.y + a3.y, inv, b.y + z.y);
    *(float2*)&out[(size_t)node * 64 + lane * 2] = r;
}

// ---------------- launch ----------------
extern "C" void kernel_launch(void* const* d_in, const int* in_sizes, int n_in,
                              void* d_out, int out_size) {
    const float* x = (const float*)d_in[0];
    const int* ei = (const int*)d_in[1];          // int32 edge_index [2, NE]
    const float* Wl0 = (const float*)d_in[2];
    const float* bl0 = (const float*)d_in[3];
    const float* Wr0 = (const float*)d_in[4];
    const float* Wl1 = (const float*)d_in[5];
    const float* bl1 = (const float*)d_in[6];
    const float* Wr1 = (const float*)d_in[7];
    float* out = (float*)d_out;

    static void* cnt_ptr = nullptr;
    if (!cnt_ptr) cudaGetSymbolAddress(&cnt_ptr, g_cnt);

    // CSR build (every launch; graph-replay safe; single stream)
    cudaMemsetAsync(cnt_ptr, 0, NN * sizeof(int));
    k_count<<<(NE + 255) / 256, 256>>>(ei, x);   // + fused x->fp16
    k_scanA<<<NPART, 1024>>>();
    k_scanB<<<1, 128>>>();
    k_scanC<<<NPART, 1024>>>();
    k_scatter<<<(NE + 255) / 256, 256>>>(ei);
    k_pack<<<(256 * 128 + 255) / 256, 256>>>(Wl0, Wr0, Wl1, Wr1);

    int mt = (NN + 127) / 128;  // 782
    // m016 = mean(x16[src])
    k_aggx<<<(NN + 7) / 8, 256>>>();
    // h16 = relu(m016 @ Wl0 + x16 @ Wr0 + b0)   (fp16 MMA, cp.async pipeline)
    k_gemm<0><<<mt, 256>>>(bl0);
    // y16 = h @ Wl1 (fp16), z1 = h @ Wr1 (fp32)
    k_gemm<1><<<mt, 256>>>(bl1);
    // out = mean_agg(y16) + b1 + z1
    k_agg2<<<(NN + 7) / 8, 256>>>(bl1, out);
}